// round 6
// baseline (speedup 1.0000x reference)
#include <cuda_runtime.h>
#include <cstdint>

#define BB 8
#define TT 4096
#define EE 1024
#define HH 128
#define MM (BB*TT)

// ---------------------------------------------------------------------------
// Scratch (tf32, pre-packed into mma.sync fragment order):
// g_q: per 128-row tile: [rb*16+s][lane][4 words]  (A-frags)
// g_k: per 64-row kv tile: [j*16+s][lane][2 words] (B-frags, kv cols permuted
//      pi(c)=2c / 2(c-4)+1 so the S C-layout equals the PV A-frag order)
// g_v: per 64-row kv tile: [ht*8+skv][lane][2 words]
// g_wp: W B-frags: [by][kc 0..31][J 0..15][s 0..3][lane][2 words]
// ---------------------------------------------------------------------------
static __device__ __align__(16) float g_q[(size_t)MM * HH];
static __device__ __align__(16) float g_k[(size_t)MM * HH];
static __device__ __align__(16) float g_v[(size_t)MM * HH];
static __device__ __align__(16) float g_wp[3u * EE * HH];

__device__ __forceinline__ unsigned f2tf(float f) {
    unsigned u;
    asm("cvt.rna.tf32.f32 %0, %1;" : "=r"(u) : "f"(f));
    return u;
}

__device__ __forceinline__ void mma_tf32(float4& d, const uint4& a, const uint2& b) {
    asm volatile(
        "mma.sync.aligned.m16n8k8.row.col.f32.tf32.tf32.f32 "
        "{%0,%1,%2,%3}, {%4,%5,%6,%7}, {%8,%9}, {%0,%1,%2,%3};"
        : "+f"(d.x), "+f"(d.y), "+f"(d.z), "+f"(d.w)
        : "r"(a.x), "r"(a.y), "r"(a.z), "r"(a.w), "r"(b.x), "r"(b.y));
}

__device__ __forceinline__ void cpasync16(void* sdst, const void* gsrc) {
    unsigned s = (unsigned)__cvta_generic_to_shared(sdst);
    asm volatile("cp.async.cg.shared.global [%0], [%1], 16;" :: "r"(s), "l"(gsrc));
}
#define CP_COMMIT() asm volatile("cp.async.commit_group;")
template <int N> __device__ __forceinline__ void cp_wait() {
    asm volatile("cp.async.wait_group %0;" :: "n"(N));
}

// ---------------------------------------------------------------------------
// Kernel 0: one-shot W pre-pack into B-frag tf32 layout.
// ---------------------------------------------------------------------------
__global__ __launch_bounds__(256) void wpack_kernel(
    const float* __restrict__ Wq, const float* __restrict__ Wk,
    const float* __restrict__ Wv)
{
    const int kc = blockIdx.x;
    const int by = blockIdx.y;
    const float* W = (by == 0) ? Wq : (by == 1) ? Wk : Wv;
    unsigned* dst = (unsigned*)(g_wp + (size_t)by * (EE * HH) + kc * 4096);
    const int t = threadIdx.x;
#pragma unroll
    for (int u = 0; u < 8; u++) {
        int idx = u * 256 + t;
        int J = idx >> 7, s = (idx >> 5) & 3, lane = idx & 31;
        int g = lane >> 2, tig = lane & 3;
        int k0 = kc * 32 + s * 8 + tig;
        int n  = J * 8 + g;
        dst[idx * 2]     = f2tf(W[(size_t)k0 * HH + n]);
        dst[idx * 2 + 1] = f2tf(W[(size_t)(k0 + 4) * HH + n]);
    }
}

// ---------------------------------------------------------------------------
// Kernel 1: FUSED QKV GEMM. One CTA (512 thr, 16 warps) computes q,k,v for
// 128 rows: 48 j-columns total (j' = q 0..15 | k 16..31 | v 32..47).
// Warp = (rg 0..7 rows, cg 0..1: 24 j's). x gathered ONCE per chunk,
// reused for all three outputs. W from g_wp (contiguous LDS.64, no cvt).
// smem: xs[2] 128x36f + wf[2] 12288f = 33792 f = 135168 B (1 CTA/SM).
// ---------------------------------------------------------------------------
#define XST 36
#define XBUF (128*XST)     // 4608
#define WBUF3 12288
#define QKV_SMEM ((2*XBUF + 2*WBUF3) * 4)
#define SP 132

__global__ __launch_bounds__(512, 1) void qkv_fused_kernel(
    const float* __restrict__ x,
    const float* __restrict__ bq, const float* __restrict__ bk,
    const float* __restrict__ bv)
{
    extern __shared__ float smq[];
    float* xsb[2] = { smq,           smq + XBUF };
    float* wsb[2] = { smq + 2*XBUF,  smq + 2*XBUF + WBUF3 };
    float* sp = smq;   // epilogue reuse (16896 f < 33792 f)

    const int t    = threadIdx.x;
    const int w    = t >> 5;       // 0..15
    const int lane = t & 31;
    const int g    = lane >> 2;
    const int tig  = lane & 3;
    const int rg   = w & 7;        // 8 row groups of 16
    const int cg   = w >> 3;       // 2 col groups of 24 j's
    const int m0   = blockIdx.x * 128;
    const int bx   = blockIdx.x;

    float4 acc[24];
#pragma unroll
    for (int j = 0; j < 24; j++) acc[j] = make_float4(0.f, 0.f, 0.f, 0.f);

#define LOAD_CHUNK(KC, BUF) do {                                              \
        float* xd = xsb[BUF]; float* wd = wsb[BUF];                           \
        _Pragma("unroll")                                                     \
        for (int u = 0; u < 2; u++) {                                         \
            int idx = u * 512 + t;                                            \
            int row = idx >> 3, c4 = (idx & 7) * 4;                           \
            cpasync16(xd + row * XST + c4,                                    \
                      x + (size_t)(m0 + row) * EE + (KC) + c4);               \
        }                                                                     \
        _Pragma("unroll")                                                     \
        for (int u = 0; u < 6; u++) {                                         \
            int idx = u * 512 + t;            /* f4 index 0..3071 */          \
            cpasync16(wd + idx * 4,                                           \
                      g_wp + (size_t)(idx >> 10) * (EE * HH)                  \
                           + ((KC) >> 5) * 4096 + (idx & 1023) * 4);          \
        }                                                                     \
        CP_COMMIT();                                                          \
    } while (0)

    LOAD_CHUNK(0, 0);

    for (int c = 0; c < 32; c++) {
        const int buf = c & 1;
        if (c < 31) { LOAD_CHUNK((c + 1) * 32, buf ^ 1); cp_wait<1>(); }
        else        { cp_wait<0>(); }
        __syncthreads();

        const float* xb = xsb[buf];
        const uint2* wb2 = (const uint2*)wsb[buf];
#pragma unroll
        for (int s = 0; s < 4; s++) {
            const float* xr0 = xb + (rg*16 + g)     * XST + s*8 + tig;
            const float* xr1 = xb + (rg*16 + g + 8) * XST + s*8 + tig;
            uint4 a;
            a.x = f2tf(xr0[0]); a.y = f2tf(xr1[0]);
            a.z = f2tf(xr0[4]); a.w = f2tf(xr1[4]);
#pragma unroll
            for (int j = 0; j < 24; j++) {
                uint2 bf = wb2[(((cg * 24 + j) * 4) + s) * 32 + lane];
                mma_tf32(acc[j], a, bf);
            }
        }
        __syncthreads();
    }

    // ---- epilogue: three phases (q, k, v): write sp -> pack -> store ----
    const float SCALE = 0.08838834764831845f;
#pragma unroll 1
    for (int o = 0; o < 3; o++) {
        const float* bias = (o == 0) ? bq : (o == 1) ? bk : bv;
        const float sc = (o == 0) ? SCALE : 1.0f;
#pragma unroll
        for (int j = 0; j < 24; j++) {
            int jp = cg * 24 + j;
            if ((jp >> 4) == o) {
                int c0 = (jp - 16 * o) * 8 + 2 * tig;
                int r0 = rg * 16 + g;
                float b0 = __ldg(bias + c0), b1 = __ldg(bias + c0 + 1);
                float4 a = acc[j];
                *(float2*)&sp[r0 * SP + c0]       = make_float2((a.x + b0) * sc, (a.y + b1) * sc);
                *(float2*)&sp[(r0 + 8) * SP + c0] = make_float2((a.z + b0) * sc, (a.w + b1) * sc);
            }
        }
        __syncthreads();

        if (o == 0) {
            unsigned* dst = (unsigned*)(g_q + (size_t)bx * 16384);
#pragma unroll
            for (int i = 0; i < 8; i++) {
                int idx = w * 8 + i;          // 0..127 = rb*16+s
                int rb = idx >> 4, s = idx & 15;
                float v0 = sp[(rb * 16 + g)     * SP + 8 * s + tig];
                float v1 = sp[(rb * 16 + g + 8) * SP + 8 * s + tig];
                float v2 = sp[(rb * 16 + g)     * SP + 8 * s + tig + 4];
                float v3 = sp[(rb * 16 + g + 8) * SP + 8 * s + tig + 4];
                *(uint4*)(dst + (idx * 32 + lane) * 4) =
                    make_uint4(f2tf(v0), f2tf(v1), f2tf(v2), f2tf(v3));
            }
        } else if (o == 1) {
            const int pg = (g >> 1) + ((g & 1) << 2);   // pi^-1(g)
#pragma unroll
            for (int it = 0; it < 16; it++) {
                int idx = w * 16 + it;        // 0..255
                int kt = idx >> 7, j = (idx >> 4) & 7, s = idx & 15;
                int row = kt * 64 + 8 * j + pg;
                float v0 = sp[row * SP + 8 * s + tig];
                float v1 = sp[row * SP + 8 * s + tig + 4];
                unsigned* dst = (unsigned*)(g_k + (size_t)(2 * bx + kt) * 8192);
                *(uint2*)(dst + ((j * 16 + s) * 32 + lane) * 2) =
                    make_uint2(f2tf(v0), f2tf(v1));
            }
        } else {
#pragma unroll
            for (int it = 0; it < 16; it++) {
                int idx = w * 16 + it;
                int kt = idx >> 7, ht = (idx >> 3) & 15, skv = idx & 7;
                float v0 = sp[(kt * 64 + 8 * skv + tig)     * SP + 8 * ht + g];
                float v1 = sp[(kt * 64 + 8 * skv + tig + 4) * SP + 8 * ht + g];
                unsigned* dst = (unsigned*)(g_v + (size_t)(2 * bx + kt) * 8192);
                *(uint2*)(dst + ((ht * 8 + skv) * 32 + lane) * 2) =
                    make_uint2(f2tf(v0), f2tf(v1));
            }
        }
        __syncthreads();
    }
}

// ---------------------------------------------------------------------------
// Kernel 2: flash attention, deferred-PV pipeline. Q in SMEM (regs freed).
// CTA = 128 q-rows, 256 threads. K,V double-buffered.
// smem: k[2] 32KB + v[2] 32KB + q 64KB = 192KB (1 CTA/SM).
// Grid 16 x 8; CTA does q-tiles (bx, 31-bx): 66 kv-iters (balanced).
// ---------------------------------------------------------------------------
#define ATT_SMEM (49152 * 4)   // 196608 B

__global__ __launch_bounds__(256, 1) void attn_mma_kernel(float* __restrict__ out)
{
    extern __shared__ float sm[];
    unsigned* kbu[2] = { (unsigned*)sm,             (unsigned*)(sm + 8192) };
    unsigned* vbu[2] = { (unsigned*)(sm + 16384),   (unsigned*)(sm + 24576) };
    unsigned* qsu    = (unsigned*)(sm + 32768);

    const int t    = threadIdx.x;
    const int w    = t >> 5;       // 0..7
    const int lane = t & 31;
    const int g    = lane >> 2;
    const int tig  = lane & 3;
    const int b    = blockIdx.y;
    const int bx   = blockIdx.x;   // 0..15

#pragma unroll 1
    for (int half = 0; half < 2; half++) {
        const int qt = half ? (31 - bx) : bx;   // 128-row q-tile

        // issue Q copy (A-frags, packed) + K(0)
        {
            const float* qg = g_q + (size_t)(b * 32 + qt) * 16384;
#pragma unroll
            for (int u = 0; u < 16; u++) {
                int idx = u * 256 + t;
                cpasync16((float*)qsu + idx * 4, qg + idx * 4);
            }
            CP_COMMIT();
            const float* kg = g_k + (size_t)(b * 64) * 8192;
#pragma unroll
            for (int u = 0; u < 8; u++) {
                int idx = u * 256 + t;
                cpasync16((float*)kbu[0] + idx * 4, kg + idx * 4);
            }
            CP_COMMIT();
        }

        float4 O[16];
#pragma unroll
        for (int ht = 0; ht < 16; ht++) O[ht] = make_float4(0.f, 0.f, 0.f, 0.f);
        float mrow[2] = {-3.0e38f, -3.0e38f};
        float lrow[2] = {0.f, 0.f};
        float aprev[2] = {1.f, 1.f};
        uint4 pa[8];

        const int ntiles = 2 * qt + 2;

#pragma unroll 1
        for (int st = 0; st < ntiles; st++) {
            const int p = st & 1;

            cp_wait<0>();          // Q + K(st) + V(st-1) complete
            __syncthreads();

            // issue V(st), K(st+1)
            {
                const float* vg = g_v + (size_t)(b * 64 + st) * 8192;
#pragma unroll
                for (int u = 0; u < 8; u++) {
                    int idx = u * 256 + t;
                    cpasync16((float*)vbu[p] + idx * 4, vg + idx * 4);
                }
                CP_COMMIT();
            }
            if (st + 1 < ntiles) {
                const float* kg = g_k + (size_t)(b * 64 + st + 1) * 8192;
#pragma unroll
                for (int u = 0; u < 8; u++) {
                    int idx = u * 256 + t;
                    cpasync16((float*)kbu[p ^ 1] + idx * 4, kg + idx * 4);
                }
                CP_COMMIT();
            }

            // ---- S = Q @ K^T  (16 x 64 per warp; Q from smem) ----
            const unsigned* ksu = kbu[p];
            float4 sa[8];
#pragma unroll
            for (int j = 0; j < 8; j++) sa[j] = make_float4(0.f, 0.f, 0.f, 0.f);
#pragma unroll
            for (int s = 0; s < 16; s++) {
                uint4 a = *(const uint4*)(qsu + ((w * 16 + s) * 32 + lane) * 4);
#pragma unroll
                for (int j = 0; j < 8; j++) {
                    uint2 bf = *(const uint2*)(ksu + ((j * 16 + s) * 32 + lane) * 2);
                    mma_tf32(sa[j], a, bf);
                }
            }

            // ---- deferred: O *= alpha(st-1); O += P(st-1) @ V(st-1) ----
            if (st > 0) {
#pragma unroll
                for (int ht = 0; ht < 16; ht++) {
                    O[ht].x *= aprev[0]; O[ht].y *= aprev[0];
                    O[ht].z *= aprev[1]; O[ht].w *= aprev[1];
                }
                const unsigned* vsu = vbu[p ^ 1];
#pragma unroll
                for (int skv = 0; skv < 8; skv++) {
#pragma unroll
                    for (int ht = 0; ht < 16; ht++) {
                        uint2 bf = *(const uint2*)(vsu + ((ht * 8 + skv) * 32 + lane) * 2);
                        mma_tf32(O[ht], pa[skv], bf);
                    }
                }
            }

            // ---- causal mask (permuted K cols) ----
            if (st >= 2 * qt) {
                const int rbase = qt * 128 + w * 16 + g;
#pragma unroll
                for (int j = 0; j < 8; j++) {
                    int kvx = st * 64 + 8 * j + tig;
                    if (kvx     > rbase)     sa[j].x = -1.0e30f;
                    if (kvx + 4 > rbase)     sa[j].y = -1.0e30f;
                    if (kvx     > rbase + 8) sa[j].z = -1.0e30f;
                    if (kvx + 4 > rbase + 8) sa[j].w = -1.0e30f;
                }
            }

            // ---- softmax(st) ----
#pragma unroll
            for (int h = 0; h < 2; h++) {
                float lm = -3.0e38f;
#pragma unroll
                for (int j = 0; j < 8; j++) {
                    float v0 = h ? sa[j].z : sa[j].x;
                    float v1 = h ? sa[j].w : sa[j].y;
                    lm = fmaxf(lm, fmaxf(v0, v1));
                }
                lm = fmaxf(lm, __shfl_xor_sync(0xffffffffu, lm, 1));
                lm = fmaxf(lm, __shfl_xor_sync(0xffffffffu, lm, 2));
                float mn = fmaxf(mrow[h], lm);
                aprev[h] = __expf(mrow[h] - mn);
                mrow[h] = mn;
                float ls = 0.f;
#pragma unroll
                for (int j = 0; j < 8; j++) {
                    float v0 = h ? sa[j].z : sa[j].x;
                    float v1 = h ? sa[j].w : sa[j].y;
                    v0 = __expf(v0 - mn);
                    v1 = __expf(v1 - mn);
                    if (h) { sa[j].z = v0; sa[j].w = v1; }
                    else   { sa[j].x = v0; sa[j].y = v1; }
                    ls += v0 + v1;
                }
                ls += __shfl_xor_sync(0xffffffffu, ls, 1);
                ls += __shfl_xor_sync(0xffffffffu, ls, 2);
                lrow[h] = lrow[h] * aprev[h] + ls;
            }
#pragma unroll
            for (int j = 0; j < 8; j++)
                pa[j] = make_uint4(f2tf(sa[j].x), f2tf(sa[j].z),
                                   f2tf(sa[j].y), f2tf(sa[j].w));
        }

        // ---- epilogue: final deferred PV, normalize, store ----
        cp_wait<0>();
        __syncthreads();
        {
#pragma unroll
            for (int ht = 0; ht < 16; ht++) {
                O[ht].x *= aprev[0]; O[ht].y *= aprev[0];
                O[ht].z *= aprev[1]; O[ht].w *= aprev[1];
            }
            const unsigned* vsu = vbu[(ntiles - 1) & 1];
#pragma unroll
            for (int skv = 0; skv < 8; skv++) {
#pragma unroll
                for (int ht = 0; ht < 16; ht++) {
                    uint2 bf = *(const uint2*)(vsu + ((ht * 8 + skv) * 32 + lane) * 2);
                    mma_tf32(O[ht], pa[skv], bf);
                }
            }
        }
        __syncthreads();

        const float inv0 = 1.0f / lrow[0];
        const float inv1 = 1.0f / lrow[1];
        const int r0 = qt * 128 + w * 16 + g;
        float* o0 = out + ((size_t)b * TT + r0) * HH;
        float* o1 = o0 + 8 * HH;
#pragma unroll
        for (int ht = 0; ht < 16; ht++) {
            int col = ht * 8 + 2 * tig;
            *(float2*)(o0 + col) = make_float2(O[ht].x * inv0, O[ht].y * inv0);
            *(float2*)(o1 + col) = make_float2(O[ht].z * inv1, O[ht].w * inv1);
        }
    }
}

// ---------------------------------------------------------------------------
extern "C" void kernel_launch(void* const* d_in, const int* in_sizes, int n_in,
                              void* d_out, int out_size)
{
    const float* x  = (const float*)d_in[0];
    const float* Wq = (const float*)d_in[1];
    const float* bq = (const float*)d_in[2];
    const float* Wk = (const float*)d_in[3];
    const float* bk = (const float*)d_in[4];
    const float* Wv = (const float*)d_in[5];
    const float* bv = (const float*)d_in[6];
    float* out = (float*)d_out;

    cudaFuncSetAttribute(qkv_fused_kernel,
                         cudaFuncAttributeMaxDynamicSharedMemorySize, QKV_SMEM);
    cudaFuncSetAttribute(attn_mma_kernel,
                         cudaFuncAttributeMaxDynamicSharedMemorySize, ATT_SMEM);

    wpack_kernel<<<dim3(32, 3), 256>>>(Wq, Wk, Wv);
    qkv_fused_kernel<<<MM / 128, 512, QKV_SMEM>>>(x, bq, bk, bv);
    attn_mma_kernel<<<dim3(16, BB), 256, ATT_SMEM>>>(out);
}

// round 7
// speedup vs baseline: 1.0142x; 1.0142x over previous
#include <cuda_runtime.h>
#include <cstdint>

#define BB 8
#define TT 4096
#define EE 1024
#define HH 128
#define MM (BB*TT)

// ---------------------------------------------------------------------------
// Scratch (tf32, pre-packed into mma.sync fragment order):
// g_q: per 128-row tile: [rb*16+s][lane][4 words]  (A-frags)
// g_k: per 64-row kv tile: [j*16+s][lane][2 words] (B-frags, kv cols permuted
//      pi(c)=2c / 2(c-4)+1 so the S C-layout equals the PV A-frag order)
// g_v: per 64-row kv tile: [ht*8+skv][lane][2 words]
// g_wp: W B-frags: [by][kc 0..31][J 0..15][s 0..3][lane][2 words]
// ---------------------------------------------------------------------------
static __device__ __align__(16) float g_q[(size_t)MM * HH];
static __device__ __align__(16) float g_k[(size_t)MM * HH];
static __device__ __align__(16) float g_v[(size_t)MM * HH];
static __device__ __align__(16) float g_wp[3u * EE * HH];

__device__ __forceinline__ unsigned f2tf(float f) {
    unsigned u;
    asm("cvt.rna.tf32.f32 %0, %1;" : "=r"(u) : "f"(f));
    return u;
}

__device__ __forceinline__ void mma_tf32(float4& d, const uint4& a, const uint2& b) {
    asm volatile(
        "mma.sync.aligned.m16n8k8.row.col.f32.tf32.tf32.f32 "
        "{%0,%1,%2,%3}, {%4,%5,%6,%7}, {%8,%9}, {%0,%1,%2,%3};"
        : "+f"(d.x), "+f"(d.y), "+f"(d.z), "+f"(d.w)
        : "r"(a.x), "r"(a.y), "r"(a.z), "r"(a.w), "r"(b.x), "r"(b.y));
}

__device__ __forceinline__ void cpasync16(void* sdst, const void* gsrc) {
    unsigned s = (unsigned)__cvta_generic_to_shared(sdst);
    asm volatile("cp.async.cg.shared.global [%0], [%1], 16;" :: "r"(s), "l"(gsrc));
}
#define CP_COMMIT() asm volatile("cp.async.commit_group;")
template <int N> __device__ __forceinline__ void cp_wait() {
    asm volatile("cp.async.wait_group %0;" :: "n"(N));
}

// ---------------------------------------------------------------------------
// Kernel 0: one-shot W pre-pack into B-frag tf32 layout.
// ---------------------------------------------------------------------------
__global__ __launch_bounds__(256) void wpack_kernel(
    const float* __restrict__ Wq, const float* __restrict__ Wk,
    const float* __restrict__ Wv)
{
    const int kc = blockIdx.x;
    const int by = blockIdx.y;
    const float* W = (by == 0) ? Wq : (by == 1) ? Wk : Wv;
    unsigned* dst = (unsigned*)(g_wp + (size_t)by * (EE * HH) + kc * 4096);
    const int t = threadIdx.x;
#pragma unroll
    for (int u = 0; u < 8; u++) {
        int idx = u * 256 + t;
        int J = idx >> 7, s = (idx >> 5) & 3, lane = idx & 31;
        int g = lane >> 2, tig = lane & 3;
        int k0 = kc * 32 + s * 8 + tig;
        int n  = J * 8 + g;
        dst[idx * 2]     = f2tf(W[(size_t)k0 * HH + n]);
        dst[idx * 2 + 1] = f2tf(W[(size_t)(k0 + 4) * HH + n]);
    }
}

// ---------------------------------------------------------------------------
// Kernel 1: QKV GEMM (R5 version — 256 threads, per-output grid slice,
// no spills). x via padded smem + gather/cvt; W via pre-packed frags.
// smem: xs[2] 128x36f + wf[2] 4096f = 17408 f; epilogue sp 128x132.
// ---------------------------------------------------------------------------
#define XST 36
#define XBUF (128*XST)     // 4608
#define WBUF 4096
#define QKV_SMEM (17408*4)
#define SP 132

__global__ __launch_bounds__(256, 2) void qkv_mma_kernel(
    const float* __restrict__ x,
    const float* __restrict__ bq, const float* __restrict__ bk,
    const float* __restrict__ bv)
{
    extern __shared__ float smq[];
    float* xsb[2] = { smq,           smq + XBUF };
    float* wsb[2] = { smq + 2*XBUF,  smq + 2*XBUF + WBUF };
    float* sp = smq;

    const int by = blockIdx.y;
    const float* bias = (by == 0) ? bq : (by == 1) ? bk : bv;
    float* outg = (by == 0) ? g_q : (by == 1) ? g_k : g_v;
    const float* wp = g_wp + (size_t)by * (EE * HH);

    const int t    = threadIdx.x;
    const int w    = t >> 5;
    const int lane = t & 31;
    const int g    = lane >> 2;
    const int tig  = lane & 3;
    const int rg   = w & 3;
    const int cg   = w >> 2;
    const int m0   = blockIdx.x * 128;

    float4 acc[2][8];
#pragma unroll
    for (int i = 0; i < 2; i++)
#pragma unroll
        for (int j = 0; j < 8; j++) acc[i][j] = make_float4(0.f, 0.f, 0.f, 0.f);

#define LOAD_CHUNK(KC, BUF) do {                                              \
        float* xd = xsb[BUF]; float* wd = wsb[BUF];                           \
        _Pragma("unroll")                                                     \
        for (int u = 0; u < 4; u++) {                                         \
            int idx = u * 256 + t;                                            \
            int row = idx >> 3, c4 = (idx & 7) * 4;                           \
            cpasync16(xd + row * XST + c4,                                    \
                      x + (size_t)(m0 + row) * EE + (KC) + c4);               \
        }                                                                     \
        _Pragma("unroll")                                                     \
        for (int u = 0; u < 4; u++) {                                         \
            int idx = u * 256 + t;                                            \
            cpasync16(wd + idx * 4, wp + ((KC) >> 5) * 4096 + idx * 4);       \
        }                                                                     \
        CP_COMMIT();                                                          \
    } while (0)

    LOAD_CHUNK(0, 0);

    for (int c = 0; c < 32; c++) {
        const int buf = c & 1;
        if (c < 31) { LOAD_CHUNK((c + 1) * 32, buf ^ 1); cp_wait<1>(); }
        else        { cp_wait<0>(); }
        __syncthreads();

        const float* xb = xsb[buf];
        const uint2* wb2 = (const uint2*)wsb[buf];
#pragma unroll
        for (int s = 0; s < 4; s++) {
            uint4 a[2];
#pragma unroll
            for (int i = 0; i < 2; i++) {
                const float* xr0 = xb + ((2*rg + i)*16 + g)     * XST + s*8 + tig;
                const float* xr1 = xb + ((2*rg + i)*16 + g + 8) * XST + s*8 + tig;
                a[i].x = f2tf(xr0[0]); a[i].y = f2tf(xr1[0]);
                a[i].z = f2tf(xr0[4]); a[i].w = f2tf(xr1[4]);
            }
#pragma unroll
            for (int j = 0; j < 8; j++) {
                uint2 bf = wb2[(((cg * 8 + j) * 4 + s) * 32) + lane];
                mma_tf32(acc[0][j], a[0], bf);
                mma_tf32(acc[1][j], a[1], bf);
            }
        }
        __syncthreads();
    }

    // ---- epilogue: bias (+q scale) -> plain smem -> pack ----
    const float SCALE = 0.08838834764831845f;
    const float sc = (by == 0) ? SCALE : 1.0f;
#pragma unroll
    for (int i = 0; i < 2; i++) {
        int r0 = rg * 32 + i * 16 + g;
#pragma unroll
        for (int j = 0; j < 8; j++) {
            int c0 = cg * 64 + j * 8 + 2 * tig;
            float b0 = __ldg(bias + c0), b1 = __ldg(bias + c0 + 1);
            float4 a = acc[i][j];
            *(float2*)&sp[r0 * SP + c0]       = make_float2((a.x + b0) * sc, (a.y + b1) * sc);
            *(float2*)&sp[(r0 + 8) * SP + c0] = make_float2((a.z + b0) * sc, (a.w + b1) * sc);
        }
    }
    __syncthreads();

    const int bx = blockIdx.x;
    if (by == 0) {
        unsigned* dst = (unsigned*)(outg + (size_t)bx * 16384);
#pragma unroll
        for (int i = 0; i < 16; i++) {
            float v0 = sp[(w * 16 + g)     * SP + 8 * i + tig];
            float v1 = sp[(w * 16 + g + 8) * SP + 8 * i + tig];
            float v2 = sp[(w * 16 + g)     * SP + 8 * i + tig + 4];
            float v3 = sp[(w * 16 + g + 8) * SP + 8 * i + tig + 4];
            *(uint4*)(dst + ((w * 16 + i) * 32 + lane) * 4) =
                make_uint4(f2tf(v0), f2tf(v1), f2tf(v2), f2tf(v3));
        }
    } else if (by == 1) {
        const int pg = (g >> 1) + ((g & 1) << 2);   // pi^-1(g)
#pragma unroll
        for (int it = 0; it < 32; it++) {
            int idx = w * 32 + it;
            int kt = idx >> 7, j = (idx >> 4) & 7, s = idx & 15;
            int row = kt * 64 + 8 * j + pg;
            float v0 = sp[row * SP + 8 * s + tig];
            float v1 = sp[row * SP + 8 * s + tig + 4];
            unsigned* dst = (unsigned*)(outg + (size_t)(2 * bx + kt) * 8192);
            *(uint2*)(dst + ((j * 16 + s) * 32 + lane) * 2) = make_uint2(f2tf(v0), f2tf(v1));
        }
    } else {
#pragma unroll
        for (int it = 0; it < 32; it++) {
            int idx = w * 32 + it;
            int kt = idx >> 7, ht = (idx >> 3) & 15, skv = idx & 7;
            float v0 = sp[(kt * 64 + 8 * skv + tig)     * SP + 8 * ht + g];
            float v1 = sp[(kt * 64 + 8 * skv + tig + 4) * SP + 8 * ht + g];
            unsigned* dst = (unsigned*)(outg + (size_t)(2 * bx + kt) * 8192);
            *(uint2*)(dst + ((ht * 8 + skv) * 32 + lane) * 2) = make_uint2(f2tf(v0), f2tf(v1));
        }
    }
}

// ---------------------------------------------------------------------------
// Kernel 2: flash attention, deferred-PV pipeline, Q in SMEM (R6 version —
// regs ~190, spill-free). CTA = 128 q-rows, 256 threads. K,V double-buffered.
// smem: k[2] 32KB + v[2] 32KB + q 64KB = 192KB (1 CTA/SM).
// Grid 16 x 8; CTA does q-tiles (bx, 31-bx): 66 kv-iters (balanced).
// ---------------------------------------------------------------------------
#define ATT_SMEM (49152 * 4)   // 196608 B

__global__ __launch_bounds__(256, 1) void attn_mma_kernel(float* __restrict__ out)
{
    extern __shared__ float sm[];
    unsigned* kbu[2] = { (unsigned*)sm,             (unsigned*)(sm + 8192) };
    unsigned* vbu[2] = { (unsigned*)(sm + 16384),   (unsigned*)(sm + 24576) };
    unsigned* qsu    = (unsigned*)(sm + 32768);

    const int t    = threadIdx.x;
    const int w    = t >> 5;       // 0..7
    const int lane = t & 31;
    const int g    = lane >> 2;
    const int tig  = lane & 3;
    const int b    = blockIdx.y;
    const int bx   = blockIdx.x;   // 0..15

#pragma unroll 1
    for (int half = 0; half < 2; half++) {
        const int qt = half ? (31 - bx) : bx;   // 128-row q-tile

        // issue Q copy (A-frags, packed) + K(0)
        {
            const float* qg = g_q + (size_t)(b * 32 + qt) * 16384;
#pragma unroll
            for (int u = 0; u < 16; u++) {
                int idx = u * 256 + t;
                cpasync16((float*)qsu + idx * 4, qg + idx * 4);
            }
            CP_COMMIT();
            const float* kg = g_k + (size_t)(b * 64) * 8192;
#pragma unroll
            for (int u = 0; u < 8; u++) {
                int idx = u * 256 + t;
                cpasync16((float*)kbu[0] + idx * 4, kg + idx * 4);
            }
            CP_COMMIT();
        }

        float4 O[16];
#pragma unroll
        for (int ht = 0; ht < 16; ht++) O[ht] = make_float4(0.f, 0.f, 0.f, 0.f);
        float mrow[2] = {-3.0e38f, -3.0e38f};
        float lrow[2] = {0.f, 0.f};
        float aprev[2] = {1.f, 1.f};
        uint4 pa[8];

        const int ntiles = 2 * qt + 2;

#pragma unroll 1
        for (int st = 0; st < ntiles; st++) {
            const int p = st & 1;

            cp_wait<0>();          // Q + K(st) + V(st-1) complete
            __syncthreads();

            // issue V(st), K(st+1)
            {
                const float* vg = g_v + (size_t)(b * 64 + st) * 8192;
#pragma unroll
                for (int u = 0; u < 8; u++) {
                    int idx = u * 256 + t;
                    cpasync16((float*)vbu[p] + idx * 4, vg + idx * 4);
                }
                CP_COMMIT();
            }
            if (st + 1 < ntiles) {
                const float* kg = g_k + (size_t)(b * 64 + st + 1) * 8192;
#pragma unroll
                for (int u = 0; u < 8; u++) {
                    int idx = u * 256 + t;
                    cpasync16((float*)kbu[p ^ 1] + idx * 4, kg + idx * 4);
                }
                CP_COMMIT();
            }

            // ---- S = Q @ K^T  (16 x 64 per warp; Q from smem) ----
            const unsigned* ksu = kbu[p];
            float4 sa[8];
#pragma unroll
            for (int j = 0; j < 8; j++) sa[j] = make_float4(0.f, 0.f, 0.f, 0.f);
#pragma unroll
            for (int s = 0; s < 16; s++) {
                uint4 a = *(const uint4*)(qsu + ((w * 16 + s) * 32 + lane) * 4);
#pragma unroll
                for (int j = 0; j < 8; j++) {
                    uint2 bf = *(const uint2*)(ksu + ((j * 16 + s) * 32 + lane) * 2);
                    mma_tf32(sa[j], a, bf);
                }
            }

            // ---- deferred: O *= alpha(st-1); O += P(st-1) @ V(st-1) ----
            if (st > 0) {
#pragma unroll
                for (int ht = 0; ht < 16; ht++) {
                    O[ht].x *= aprev[0]; O[ht].y *= aprev[0];
                    O[ht].z *= aprev[1]; O[ht].w *= aprev[1];
                }
                const unsigned* vsu = vbu[p ^ 1];
#pragma unroll
                for (int skv = 0; skv < 8; skv++) {
#pragma unroll
                    for (int ht = 0; ht < 16; ht++) {
                        uint2 bf = *(const uint2*)(vsu + ((ht * 8 + skv) * 32 + lane) * 2);
                        mma_tf32(O[ht], pa[skv], bf);
                    }
                }
            }

            // ---- causal mask (permuted K cols) ----
            if (st >= 2 * qt) {
                const int rbase = qt * 128 + w * 16 + g;
#pragma unroll
                for (int j = 0; j < 8; j++) {
                    int kvx = st * 64 + 8 * j + tig;
                    if (kvx     > rbase)     sa[j].x = -1.0e30f;
                    if (kvx + 4 > rbase)     sa[j].y = -1.0e30f;
                    if (kvx     > rbase + 8) sa[j].z = -1.0e30f;
                    if (kvx + 4 > rbase + 8) sa[j].w = -1.0e30f;
                }
            }

            // ---- softmax(st) ----
#pragma unroll
            for (int h = 0; h < 2; h++) {
                float lm = -3.0e38f;
#pragma unroll
                for (int j = 0; j < 8; j++) {
                    float v0 = h ? sa[j].z : sa[j].x;
                    float v1 = h ? sa[j].w : sa[j].y;
                    lm = fmaxf(lm, fmaxf(v0, v1));
                }
                lm = fmaxf(lm, __shfl_xor_sync(0xffffffffu, lm, 1));
                lm = fmaxf(lm, __shfl_xor_sync(0xffffffffu, lm, 2));
                float mn = fmaxf(mrow[h], lm);
                aprev[h] = __expf(mrow[h] - mn);
                mrow[h] = mn;
                float ls = 0.f;
#pragma unroll
                for (int j = 0; j < 8; j++) {
                    float v0 = h ? sa[j].z : sa[j].x;
                    float v1 = h ? sa[j].w : sa[j].y;
                    v0 = __expf(v0 - mn);
                    v1 = __expf(v1 - mn);
                    if (h) { sa[j].z = v0; sa[j].w = v1; }
                    else   { sa[j].x = v0; sa[j].y = v1; }
                    ls += v0 + v1;
                }
                ls += __shfl_xor_sync(0xffffffffu, ls, 1);
                ls += __shfl_xor_sync(0xffffffffu, ls, 2);
                lrow[h] = lrow[h] * aprev[h] + ls;
            }
#pragma unroll
            for (int j = 0; j < 8; j++)
                pa[j] = make_uint4(f2tf(sa[j].x), f2tf(sa[j].z),
                                   f2tf(sa[j].y), f2tf(sa[j].w));
        }

        // ---- epilogue: final deferred PV, normalize, store ----
        cp_wait<0>();
        __syncthreads();
        {
#pragma unroll
            for (int ht = 0; ht < 16; ht++) {
                O[ht].x *= aprev[0]; O[ht].y *= aprev[0];
                O[ht].z *= aprev[1]; O[ht].w *= aprev[1];
            }
            const unsigned* vsu = vbu[(ntiles - 1) & 1];
#pragma unroll
            for (int skv = 0; skv < 8; skv++) {
#pragma unroll
                for (int ht = 0; ht < 16; ht++) {
                    uint2 bf = *(const uint2*)(vsu + ((ht * 8 + skv) * 32 + lane) * 2);
                    mma_tf32(O[ht], pa[skv], bf);
                }
            }
        }
        __syncthreads();

        const float inv0 = 1.0f / lrow[0];
        const float inv1 = 1.0f / lrow[1];
        const int r0 = qt * 128 + w * 16 + g;
        float* o0 = out + ((size_t)b * TT + r0) * HH;
        float* o1 = o0 + 8 * HH;
#pragma unroll
        for (int ht = 0; ht < 16; ht++) {
            int col = ht * 8 + 2 * tig;
            *(float2*)(o0 + col) = make_float2(O[ht].x * inv0, O[ht].y * inv0);
            *(float2*)(o1 + col) = make_float2(O[ht].z * inv1, O[ht].w * inv1);
        }
    }
}

// ---------------------------------------------------------------------------
extern "C" void kernel_launch(void* const* d_in, const int* in_sizes, int n_in,
                              void* d_out, int out_size)
{
    const float* x  = (const float*)d_in[0];
    const float* Wq = (const float*)d_in[1];
    const float* bq = (const float*)d_in[2];
    const float* Wk = (const float*)d_in[3];
    const float* bk = (const float*)d_in[4];
    const float* Wv = (const float*)d_in[5];
    const float* bv = (const float*)d_in[6];
    float* out = (float*)d_out;

    cudaFuncSetAttribute(qkv_mma_kernel,
                         cudaFuncAttributeMaxDynamicSharedMemorySize, QKV_SMEM);
    cudaFuncSetAttribute(attn_mma_kernel,
                         cudaFuncAttributeMaxDynamicSharedMemorySize, ATT_SMEM);

    wpack_kernel<<<dim3(32, 3), 256>>>(Wq, Wk, Wv);
    qkv_mma_kernel<<<dim3(MM / 128, 3), 256, QKV_SMEM>>>(x, bq, bk, bv);
    attn_mma_kernel<<<dim3(16, BB), 256, ATT_SMEM>>>(out);
}

// round 8
// speedup vs baseline: 1.0144x; 1.0002x over previous
#include <cuda_runtime.h>
#include <cstdint>

#define BB 8
#define TT 4096
#define EE 1024
#define HH 128
#define MM (BB*TT)

// ---------------------------------------------------------------------------
// Scratch (tf32, pre-packed into mma.sync fragment order):
// g_q: per 128-row tile: [rb*16+s][lane][4 words]  (A-frags)
// g_k: per 64-row kv tile: [j*16+s][lane][2 words] (B-frags, kv cols permuted
//      pi(c)=2c / 2(c-4)+1 so the S C-layout equals the PV A-frag order)
// g_v: per 64-row kv tile: [ht*8+skv][lane][2 words]
// g_wp: W B-frags: [by][kc 0..31][J 0..15][s 0..3][lane][2 words]
// ---------------------------------------------------------------------------
static __device__ __align__(16) float g_q[(size_t)MM * HH];
static __device__ __align__(16) float g_k[(size_t)MM * HH];
static __device__ __align__(16) float g_v[(size_t)MM * HH];
static __device__ __align__(16) float g_wp[3u * EE * HH];

__device__ __forceinline__ unsigned f2tf(float f) {
    unsigned u;
    asm("cvt.rna.tf32.f32 %0, %1;" : "=r"(u) : "f"(f));
    return u;
}

__device__ __forceinline__ void mma_tf32(float4& d, const uint4& a, const uint2& b) {
    asm volatile(
        "mma.sync.aligned.m16n8k8.row.col.f32.tf32.tf32.f32 "
        "{%0,%1,%2,%3}, {%4,%5,%6,%7}, {%8,%9}, {%0,%1,%2,%3};"
        : "+f"(d.x), "+f"(d.y), "+f"(d.z), "+f"(d.w)
        : "r"(a.x), "r"(a.y), "r"(a.z), "r"(a.w), "r"(b.x), "r"(b.y));
}

__device__ __forceinline__ void cpasync16(void* sdst, const void* gsrc) {
    unsigned s = (unsigned)__cvta_generic_to_shared(sdst);
    asm volatile("cp.async.cg.shared.global [%0], [%1], 16;" :: "r"(s), "l"(gsrc));
}
#define CP_COMMIT() asm volatile("cp.async.commit_group;")
template <int N> __device__ __forceinline__ void cp_wait() {
    asm volatile("cp.async.wait_group %0;" :: "n"(N));
}

// ---------------------------------------------------------------------------
// Kernel 0: one-shot W pre-pack into B-frag tf32 layout.
// ---------------------------------------------------------------------------
__global__ __launch_bounds__(256) void wpack_kernel(
    const float* __restrict__ Wq, const float* __restrict__ Wk,
    const float* __restrict__ Wv)
{
    const int kc = blockIdx.x;
    const int by = blockIdx.y;
    const float* W = (by == 0) ? Wq : (by == 1) ? Wk : Wv;
    unsigned* dst = (unsigned*)(g_wp + (size_t)by * (EE * HH) + kc * 4096);
    const int t = threadIdx.x;
#pragma unroll
    for (int u = 0; u < 8; u++) {
        int idx = u * 256 + t;
        int J = idx >> 7, s = (idx >> 5) & 3, lane = idx & 31;
        int g = lane >> 2, tig = lane & 3;
        int k0 = kc * 32 + s * 8 + tig;
        int n  = J * 8 + g;
        dst[idx * 2]     = f2tf(W[(size_t)k0 * HH + n]);
        dst[idx * 2 + 1] = f2tf(W[(size_t)(k0 + 4) * HH + n]);
    }
}

// ---------------------------------------------------------------------------
// Kernel 1: QKV GEMM (R5 version — 256 threads, per-output grid slice,
// no spills). x via padded smem + gather/cvt; W via pre-packed frags.
// smem: xs[2] 128x36f + wf[2] 4096f = 17408 f; epilogue sp 128x132.
// ---------------------------------------------------------------------------
#define XST 36
#define XBUF (128*XST)     // 4608
#define WBUF 4096
#define QKV_SMEM (17408*4)
#define SP 132

__global__ __launch_bounds__(256, 2) void qkv_mma_kernel(
    const float* __restrict__ x,
    const float* __restrict__ bq, const float* __restrict__ bk,
    const float* __restrict__ bv)
{
    extern __shared__ float smq[];
    float* xsb[2] = { smq,           smq + XBUF };
    float* wsb[2] = { smq + 2*XBUF,  smq + 2*XBUF + WBUF };
    float* sp = smq;

    const int by = blockIdx.y;
    const float* bias = (by == 0) ? bq : (by == 1) ? bk : bv;
    float* outg = (by == 0) ? g_q : (by == 1) ? g_k : g_v;
    const float* wp = g_wp + (size_t)by * (EE * HH);

    const int t    = threadIdx.x;
    const int w    = t >> 5;
    const int lane = t & 31;
    const int g    = lane >> 2;
    const int tig  = lane & 3;
    const int rg   = w & 3;
    const int cg   = w >> 2;
    const int m0   = blockIdx.x * 128;

    float4 acc[2][8];
#pragma unroll
    for (int i = 0; i < 2; i++)
#pragma unroll
        for (int j = 0; j < 8; j++) acc[i][j] = make_float4(0.f, 0.f, 0.f, 0.f);

#define LOAD_CHUNK(KC, BUF) do {                                              \
        float* xd = xsb[BUF]; float* wd = wsb[BUF];                           \
        _Pragma("unroll")                                                     \
        for (int u = 0; u < 4; u++) {                                         \
            int idx = u * 256 + t;                                            \
            int row = idx >> 3, c4 = (idx & 7) * 4;                           \
            cpasync16(xd + row * XST + c4,                                    \
                      x + (size_t)(m0 + row) * EE + (KC) + c4);               \
        }                                                                     \
        _Pragma("unroll")                                                     \
        for (int u = 0; u < 4; u++) {                                         \
            int idx = u * 256 + t;                                            \
            cpasync16(wd + idx * 4, wp + ((KC) >> 5) * 4096 + idx * 4);       \
        }                                                                     \
        CP_COMMIT();                                                          \
    } while (0)

    LOAD_CHUNK(0, 0);

    for (int c = 0; c < 32; c++) {
        const int buf = c & 1;
        if (c < 31) { LOAD_CHUNK((c + 1) * 32, buf ^ 1); cp_wait<1>(); }
        else        { cp_wait<0>(); }
        __syncthreads();

        const float* xb = xsb[buf];
        const uint2* wb2 = (const uint2*)wsb[buf];
#pragma unroll
        for (int s = 0; s < 4; s++) {
            uint4 a[2];
#pragma unroll
            for (int i = 0; i < 2; i++) {
                const float* xr0 = xb + ((2*rg + i)*16 + g)     * XST + s*8 + tig;
                const float* xr1 = xb + ((2*rg + i)*16 + g + 8) * XST + s*8 + tig;
                a[i].x = f2tf(xr0[0]); a[i].y = f2tf(xr1[0]);
                a[i].z = f2tf(xr0[4]); a[i].w = f2tf(xr1[4]);
            }
#pragma unroll
            for (int j = 0; j < 8; j++) {
                uint2 bf = wb2[(((cg * 8 + j) * 4 + s) * 32) + lane];
                mma_tf32(acc[0][j], a[0], bf);
                mma_tf32(acc[1][j], a[1], bf);
            }
        }
        __syncthreads();
    }

    // ---- epilogue: bias (+q scale) -> plain smem -> pack ----
    const float SCALE = 0.08838834764831845f;
    const float sc = (by == 0) ? SCALE : 1.0f;
#pragma unroll
    for (int i = 0; i < 2; i++) {
        int r0 = rg * 32 + i * 16 + g;
#pragma unroll
        for (int j = 0; j < 8; j++) {
            int c0 = cg * 64 + j * 8 + 2 * tig;
            float b0 = __ldg(bias + c0), b1 = __ldg(bias + c0 + 1);
            float4 a = acc[i][j];
            *(float2*)&sp[r0 * SP + c0]       = make_float2((a.x + b0) * sc, (a.y + b1) * sc);
            *(float2*)&sp[(r0 + 8) * SP + c0] = make_float2((a.z + b0) * sc, (a.w + b1) * sc);
        }
    }
    __syncthreads();

    const int bx = blockIdx.x;
    if (by == 0) {
        unsigned* dst = (unsigned*)(outg + (size_t)bx * 16384);
#pragma unroll
        for (int i = 0; i < 16; i++) {
            float v0 = sp[(w * 16 + g)     * SP + 8 * i + tig];
            float v1 = sp[(w * 16 + g + 8) * SP + 8 * i + tig];
            float v2 = sp[(w * 16 + g)     * SP + 8 * i + tig + 4];
            float v3 = sp[(w * 16 + g + 8) * SP + 8 * i + tig + 4];
            *(uint4*)(dst + ((w * 16 + i) * 32 + lane) * 4) =
                make_uint4(f2tf(v0), f2tf(v1), f2tf(v2), f2tf(v3));
        }
    } else if (by == 1) {
        const int pg = (g >> 1) + ((g & 1) << 2);   // pi^-1(g)
#pragma unroll
        for (int it = 0; it < 32; it++) {
            int idx = w * 32 + it;
            int kt = idx >> 7, j = (idx >> 4) & 7, s = idx & 15;
            int row = kt * 64 + 8 * j + pg;
            float v0 = sp[row * SP + 8 * s + tig];
            float v1 = sp[row * SP + 8 * s + tig + 4];
            unsigned* dst = (unsigned*)(outg + (size_t)(2 * bx + kt) * 8192);
            *(uint2*)(dst + ((j * 16 + s) * 32 + lane) * 2) = make_uint2(f2tf(v0), f2tf(v1));
        }
    } else {
#pragma unroll
        for (int it = 0; it < 32; it++) {
            int idx = w * 32 + it;
            int kt = idx >> 7, ht = (idx >> 3) & 15, skv = idx & 7;
            float v0 = sp[(kt * 64 + 8 * skv + tig)     * SP + 8 * ht + g];
            float v1 = sp[(kt * 64 + 8 * skv + tig + 4) * SP + 8 * ht + g];
            unsigned* dst = (unsigned*)(outg + (size_t)(2 * bx + kt) * 8192);
            *(uint2*)(dst + ((ht * 8 + skv) * 32 + lane) * 2) = make_uint2(f2tf(v0), f2tf(v1));
        }
    }
}

// ---------------------------------------------------------------------------
// Kernel 2: flash attention, deferred-PV pipeline, Q in SMEM (R6 version —
// regs ~190, spill-free). CTA = 128 q-rows, 256 threads. K,V double-buffered.
// smem: k[2] 32KB + v[2] 32KB + q 64KB = 192KB (1 CTA/SM).
// Grid 16 x 8; CTA does q-tiles (bx, 31-bx): 66 kv-iters (balanced).
// ---------------------------------------------------------------------------
#define ATT_SMEM (49152 * 4)   // 196608 B

__global__ __launch_bounds__(256, 1) void attn_mma_kernel(float* __restrict__ out)
{
    extern __shared__ float sm[];
    unsigned* kbu[2] = { (unsigned*)sm,             (unsigned*)(sm + 8192) };
    unsigned* vbu[2] = { (unsigned*)(sm + 16384),   (unsigned*)(sm + 24576) };
    unsigned* qsu    = (unsigned*)(sm + 32768);

    const int t    = threadIdx.x;
    const int w    = t >> 5;       // 0..7
    const int lane = t & 31;
    const int g    = lane >> 2;
    const int tig  = lane & 3;
    const int b    = blockIdx.y;
    const int bx   = blockIdx.x;   // 0..15

#pragma unroll 1
    for (int half = 0; half < 2; half++) {
        const int qt = half ? (31 - bx) : bx;   // 128-row q-tile

        // issue Q copy (A-frags, packed) + K(0)
        {
            const float* qg = g_q + (size_t)(b * 32 + qt) * 16384;
#pragma unroll
            for (int u = 0; u < 16; u++) {
                int idx = u * 256 + t;
                cpasync16((float*)qsu + idx * 4, qg + idx * 4);
            }
            CP_COMMIT();
            const float* kg = g_k + (size_t)(b * 64) * 8192;
#pragma unroll
            for (int u = 0; u < 8; u++) {
                int idx = u * 256 + t;
                cpasync16((float*)kbu[0] + idx * 4, kg + idx * 4);
            }
            CP_COMMIT();
        }

        float4 O[16];
#pragma unroll
        for (int ht = 0; ht < 16; ht++) O[ht] = make_float4(0.f, 0.f, 0.f, 0.f);
        float mrow[2] = {-3.0e38f, -3.0e38f};
        float lrow[2] = {0.f, 0.f};
        float aprev[2] = {1.f, 1.f};
        uint4 pa[8];

        const int ntiles = 2 * qt + 2;

#pragma unroll 1
        for (int st = 0; st < ntiles; st++) {
            const int p = st & 1;

            cp_wait<0>();          // Q + K(st) + V(st-1) complete
            __syncthreads();

            // issue V(st), K(st+1)
            {
                const float* vg = g_v + (size_t)(b * 64 + st) * 8192;
#pragma unroll
                for (int u = 0; u < 8; u++) {
                    int idx = u * 256 + t;
                    cpasync16((float*)vbu[p] + idx * 4, vg + idx * 4);
                }
                CP_COMMIT();
            }
            if (st + 1 < ntiles) {
                const float* kg = g_k + (size_t)(b * 64 + st + 1) * 8192;
#pragma unroll
                for (int u = 0; u < 8; u++) {
                    int idx = u * 256 + t;
                    cpasync16((float*)kbu[p ^ 1] + idx * 4, kg + idx * 4);
                }
                CP_COMMIT();
            }

            // ---- S = Q @ K^T  (16 x 64 per warp; Q from smem) ----
            const unsigned* ksu = kbu[p];
            float4 sa[8];
#pragma unroll
            for (int j = 0; j < 8; j++) sa[j] = make_float4(0.f, 0.f, 0.f, 0.f);
#pragma unroll
            for (int s = 0; s < 16; s++) {
                uint4 a = *(const uint4*)(qsu + ((w * 16 + s) * 32 + lane) * 4);
#pragma unroll
                for (int j = 0; j < 8; j++) {
                    uint2 bf = *(const uint2*)(ksu + ((j * 16 + s) * 32 + lane) * 2);
                    mma_tf32(sa[j], a, bf);
                }
            }

            // ---- deferred: O *= alpha(st-1); O += P(st-1) @ V(st-1) ----
            if (st > 0) {
#pragma unroll
                for (int ht = 0; ht < 16; ht++) {
                    O[ht].x *= aprev[0]; O[ht].y *= aprev[0];
                    O[ht].z *= aprev[1]; O[ht].w *= aprev[1];
                }
                const unsigned* vsu = vbu[p ^ 1];
#pragma unroll
                for (int skv = 0; skv < 8; skv++) {
#pragma unroll
                    for (int ht = 0; ht < 16; ht++) {
                        uint2 bf = *(const uint2*)(vsu + ((ht * 8 + skv) * 32 + lane) * 2);
                        mma_tf32(O[ht], pa[skv], bf);
                    }
                }
            }

            // ---- causal mask (permuted K cols) ----
            if (st >= 2 * qt) {
                const int rbase = qt * 128 + w * 16 + g;
#pragma unroll
                for (int j = 0; j < 8; j++) {
                    int kvx = st * 64 + 8 * j + tig;
                    if (kvx     > rbase)     sa[j].x = -1.0e30f;
                    if (kvx + 4 > rbase)     sa[j].y = -1.0e30f;
                    if (kvx     > rbase + 8) sa[j].z = -1.0e30f;
                    if (kvx + 4 > rbase + 8) sa[j].w = -1.0e30f;
                }
            }

            // ---- softmax(st) ----
#pragma unroll
            for (int h = 0; h < 2; h++) {
                float lm = -3.0e38f;
#pragma unroll
                for (int j = 0; j < 8; j++) {
                    float v0 = h ? sa[j].z : sa[j].x;
                    float v1 = h ? sa[j].w : sa[j].y;
                    lm = fmaxf(lm, fmaxf(v0, v1));
                }
                lm = fmaxf(lm, __shfl_xor_sync(0xffffffffu, lm, 1));
                lm = fmaxf(lm, __shfl_xor_sync(0xffffffffu, lm, 2));
                float mn = fmaxf(mrow[h], lm);
                aprev[h] = __expf(mrow[h] - mn);
                mrow[h] = mn;
                float ls = 0.f;
#pragma unroll
                for (int j = 0; j < 8; j++) {
                    float v0 = h ? sa[j].z : sa[j].x;
                    float v1 = h ? sa[j].w : sa[j].y;
                    v0 = __expf(v0 - mn);
                    v1 = __expf(v1 - mn);
                    if (h) { sa[j].z = v0; sa[j].w = v1; }
                    else   { sa[j].x = v0; sa[j].y = v1; }
                    ls += v0 + v1;
                }
                ls += __shfl_xor_sync(0xffffffffu, ls, 1);
                ls += __shfl_xor_sync(0xffffffffu, ls, 2);
                lrow[h] = lrow[h] * aprev[h] + ls;
            }
#pragma unroll
            for (int j = 0; j < 8; j++)
                pa[j] = make_uint4(f2tf(sa[j].x), f2tf(sa[j].z),
                                   f2tf(sa[j].y), f2tf(sa[j].w));
        }

        // ---- epilogue: final deferred PV, normalize, store ----
        cp_wait<0>();
        __syncthreads();
        {
#pragma unroll
            for (int ht = 0; ht < 16; ht++) {
                O[ht].x *= aprev[0]; O[ht].y *= aprev[0];
                O[ht].z *= aprev[1]; O[ht].w *= aprev[1];
            }
            const unsigned* vsu = vbu[(ntiles - 1) & 1];
#pragma unroll
            for (int skv = 0; skv < 8; skv++) {
#pragma unroll
                for (int ht = 0; ht < 16; ht++) {
                    uint2 bf = *(const uint2*)(vsu + ((ht * 8 + skv) * 32 + lane) * 2);
                    mma_tf32(O[ht], pa[skv], bf);
                }
            }
        }
        __syncthreads();

        const float inv0 = 1.0f / lrow[0];
        const float inv1 = 1.0f / lrow[1];
        const int r0 = qt * 128 + w * 16 + g;
        float* o0 = out + ((size_t)b * TT + r0) * HH;
        float* o1 = o0 + 8 * HH;
#pragma unroll
        for (int ht = 0; ht < 16; ht++) {
            int col = ht * 8 + 2 * tig;
            *(float2*)(o0 + col) = make_float2(O[ht].x * inv0, O[ht].y * inv0);
            *(float2*)(o1 + col) = make_float2(O[ht].z * inv1, O[ht].w * inv1);
        }
    }
}

// ---------------------------------------------------------------------------
extern "C" void kernel_launch(void* const* d_in, const int* in_sizes, int n_in,
                              void* d_out, int out_size)
{
    const float* x  = (const float*)d_in[0];
    const float* Wq = (const float*)d_in[1];
    const float* bq = (const float*)d_in[2];
    const float* Wk = (const float*)d_in[3];
    const float* bk = (const float*)d_in[4];
    const float* Wv = (const float*)d_in[5];
    const float* bv = (const float*)d_in[6];
    float* out = (float*)d_out;

    cudaFuncSetAttribute(qkv_mma_kernel,
                         cudaFuncAttributeMaxDynamicSharedMemorySize, QKV_SMEM);
    cudaFuncSetAttribute(attn_mma_kernel,
                         cudaFuncAttributeMaxDynamicSharedMemorySize, ATT_SMEM);

    wpack_kernel<<<dim3(32, 3), 256>>>(Wq, Wk, Wv);
    qkv_mma_kernel<<<dim3(MM / 128, 3), 256, QKV_SMEM>>>(x, bq, bk, bv);
    attn_mma_kernel<<<dim3(16, BB), 256, ATT_SMEM>>>(out);
}

// round 9
// speedup vs baseline: 1.0884x; 1.0730x over previous
#include <cuda_runtime.h>
#include <cstdint>

#define BB 8
#define TT 4096
#define EE 1024
#define HH 128
#define MM (BB*TT)

// ---------------------------------------------------------------------------
// Scratch (tf32, pre-packed into mma.sync fragment order):
// g_q: per 128-row tile: [rb*16+s][lane][4 words]  (A-frags)
// g_k: per 64-row kv tile: [j*16+s][lane][2 words] (B-frags, kv cols permuted
//      pi(c)=2c / 2(c-4)+1 so the S C-layout equals the PV A-frag order)
// g_v: per 64-row kv tile: [ht*8+skv][lane][2 words]
// g_wp: W B-frags: [by][kc 0..31][J 0..15][s 0..3][lane][2 words]
// ---------------------------------------------------------------------------
static __device__ __align__(16) float g_q[(size_t)MM * HH];
static __device__ __align__(16) float g_k[(size_t)MM * HH];
static __device__ __align__(16) float g_v[(size_t)MM * HH];
static __device__ __align__(16) float g_wp[3u * EE * HH];

__device__ __forceinline__ unsigned f2tf(float f) {
    unsigned u;
    asm("cvt.rna.tf32.f32 %0, %1;" : "=r"(u) : "f"(f));
    return u;
}

__device__ __forceinline__ void mma_tf32(float4& d, const uint4& a, const uint2& b) {
    asm volatile(
        "mma.sync.aligned.m16n8k8.row.col.f32.tf32.tf32.f32 "
        "{%0,%1,%2,%3}, {%4,%5,%6,%7}, {%8,%9}, {%0,%1,%2,%3};"
        : "+f"(d.x), "+f"(d.y), "+f"(d.z), "+f"(d.w)
        : "r"(a.x), "r"(a.y), "r"(a.z), "r"(a.w), "r"(b.x), "r"(b.y));
}

__device__ __forceinline__ void cpasync16(void* sdst, const void* gsrc) {
    unsigned s = (unsigned)__cvta_generic_to_shared(sdst);
    asm volatile("cp.async.cg.shared.global [%0], [%1], 16;" :: "r"(s), "l"(gsrc));
}
#define CP_COMMIT() asm volatile("cp.async.commit_group;")
template <int N> __device__ __forceinline__ void cp_wait() {
    asm volatile("cp.async.wait_group %0;" :: "n"(N));
}

// ---------------------------------------------------------------------------
// Kernel 0: one-shot W pre-pack into B-frag tf32 layout.
// ---------------------------------------------------------------------------
__global__ __launch_bounds__(256) void wpack_kernel(
    const float* __restrict__ Wq, const float* __restrict__ Wk,
    const float* __restrict__ Wv)
{
    const int kc = blockIdx.x;
    const int by = blockIdx.y;
    const float* W = (by == 0) ? Wq : (by == 1) ? Wk : Wv;
    unsigned* dst = (unsigned*)(g_wp + (size_t)by * (EE * HH) + kc * 4096);
    const int t = threadIdx.x;
#pragma unroll
    for (int u = 0; u < 8; u++) {
        int idx = u * 256 + t;
        int J = idx >> 7, s = (idx >> 5) & 3, lane = idx & 31;
        int g = lane >> 2, tig = lane & 3;
        int k0 = kc * 32 + s * 8 + tig;
        int n  = J * 8 + g;
        dst[idx * 2]     = f2tf(W[(size_t)k0 * HH + n]);
        dst[idx * 2 + 1] = f2tf(W[(size_t)(k0 + 4) * HH + n]);
    }
}

// ---------------------------------------------------------------------------
// Kernel 1: QKV GEMM (R5 version — validated best). 256 threads, per-output
// grid slice. x via padded smem + gather/cvt; W via pre-packed frags.
// ---------------------------------------------------------------------------
#define XST 36
#define XBUF (128*XST)     // 4608
#define WBUF 4096
#define QKV_SMEM (17408*4)
#define SP 132

__global__ __launch_bounds__(256, 2) void qkv_mma_kernel(
    const float* __restrict__ x,
    const float* __restrict__ bq, const float* __restrict__ bk,
    const float* __restrict__ bv)
{
    extern __shared__ float smq[];
    float* xsb[2] = { smq,           smq + XBUF };
    float* wsb[2] = { smq + 2*XBUF,  smq + 2*XBUF + WBUF };
    float* sp = smq;

    const int by = blockIdx.y;
    const float* bias = (by == 0) ? bq : (by == 1) ? bk : bv;
    float* outg = (by == 0) ? g_q : (by == 1) ? g_k : g_v;
    const float* wp = g_wp + (size_t)by * (EE * HH);

    const int t    = threadIdx.x;
    const int w    = t >> 5;
    const int lane = t & 31;
    const int g    = lane >> 2;
    const int tig  = lane & 3;
    const int rg   = w & 3;
    const int cg   = w >> 2;
    const int m0   = blockIdx.x * 128;

    float4 acc[2][8];
#pragma unroll
    for (int i = 0; i < 2; i++)
#pragma unroll
        for (int j = 0; j < 8; j++) acc[i][j] = make_float4(0.f, 0.f, 0.f, 0.f);

#define LOAD_CHUNK(KC, BUF) do {                                              \
        float* xd = xsb[BUF]; float* wd = wsb[BUF];                           \
        _Pragma("unroll")                                                     \
        for (int u = 0; u < 4; u++) {                                         \
            int idx = u * 256 + t;                                            \
            int row = idx >> 3, c4 = (idx & 7) * 4;                           \
            cpasync16(xd + row * XST + c4,                                    \
                      x + (size_t)(m0 + row) * EE + (KC) + c4);               \
        }                                                                     \
        _Pragma("unroll")                                                     \
        for (int u = 0; u < 4; u++) {                                         \
            int idx = u * 256 + t;                                            \
            cpasync16(wd + idx * 4, wp + ((KC) >> 5) * 4096 + idx * 4);       \
        }                                                                     \
        CP_COMMIT();                                                          \
    } while (0)

    LOAD_CHUNK(0, 0);

    for (int c = 0; c < 32; c++) {
        const int buf = c & 1;
        if (c < 31) { LOAD_CHUNK((c + 1) * 32, buf ^ 1); cp_wait<1>(); }
        else        { cp_wait<0>(); }
        __syncthreads();

        const float* xb = xsb[buf];
        const uint2* wb2 = (const uint2*)wsb[buf];
#pragma unroll
        for (int s = 0; s < 4; s++) {
            uint4 a[2];
#pragma unroll
            for (int i = 0; i < 2; i++) {
                const float* xr0 = xb + ((2*rg + i)*16 + g)     * XST + s*8 + tig;
                const float* xr1 = xb + ((2*rg + i)*16 + g + 8) * XST + s*8 + tig;
                a[i].x = f2tf(xr0[0]); a[i].y = f2tf(xr1[0]);
                a[i].z = f2tf(xr0[4]); a[i].w = f2tf(xr1[4]);
            }
#pragma unroll
            for (int j = 0; j < 8; j++) {
                uint2 bf = wb2[(((cg * 8 + j) * 4 + s) * 32) + lane];
                mma_tf32(acc[0][j], a[0], bf);
                mma_tf32(acc[1][j], a[1], bf);
            }
        }
        __syncthreads();
    }

    const float SCALE = 0.08838834764831845f;
    const float sc = (by == 0) ? SCALE : 1.0f;
#pragma unroll
    for (int i = 0; i < 2; i++) {
        int r0 = rg * 32 + i * 16 + g;
#pragma unroll
        for (int j = 0; j < 8; j++) {
            int c0 = cg * 64 + j * 8 + 2 * tig;
            float b0 = __ldg(bias + c0), b1 = __ldg(bias + c0 + 1);
            float4 a = acc[i][j];
            *(float2*)&sp[r0 * SP + c0]       = make_float2((a.x + b0) * sc, (a.y + b1) * sc);
            *(float2*)&sp[(r0 + 8) * SP + c0] = make_float2((a.z + b0) * sc, (a.w + b1) * sc);
        }
    }
    __syncthreads();

    const int bx = blockIdx.x;
    if (by == 0) {
        unsigned* dst = (unsigned*)(outg + (size_t)bx * 16384);
#pragma unroll
        for (int i = 0; i < 16; i++) {
            float v0 = sp[(w * 16 + g)     * SP + 8 * i + tig];
            float v1 = sp[(w * 16 + g + 8) * SP + 8 * i + tig];
            float v2 = sp[(w * 16 + g)     * SP + 8 * i + tig + 4];
            float v3 = sp[(w * 16 + g + 8) * SP + 8 * i + tig + 4];
            *(uint4*)(dst + ((w * 16 + i) * 32 + lane) * 4) =
                make_uint4(f2tf(v0), f2tf(v1), f2tf(v2), f2tf(v3));
        }
    } else if (by == 1) {
        const int pg = (g >> 1) + ((g & 1) << 2);   // pi^-1(g)
#pragma unroll
        for (int it = 0; it < 32; it++) {
            int idx = w * 32 + it;
            int kt = idx >> 7, j = (idx >> 4) & 7, s = idx & 15;
            int row = kt * 64 + 8 * j + pg;
            float v0 = sp[row * SP + 8 * s + tig];
            float v1 = sp[row * SP + 8 * s + tig + 4];
            unsigned* dst = (unsigned*)(outg + (size_t)(2 * bx + kt) * 8192);
            *(uint2*)(dst + ((j * 16 + s) * 32 + lane) * 2) = make_uint2(f2tf(v0), f2tf(v1));
        }
    } else {
#pragma unroll
        for (int it = 0; it < 32; it++) {
            int idx = w * 32 + it;
            int kt = idx >> 7, ht = (idx >> 3) & 15, skv = idx & 7;
            float v0 = sp[(kt * 64 + 8 * skv + tig)     * SP + 8 * ht + g];
            float v1 = sp[(kt * 64 + 8 * skv + tig + 4) * SP + 8 * ht + g];
            unsigned* dst = (unsigned*)(outg + (size_t)(2 * bx + kt) * 8192);
            *(uint2*)(dst + ((ht * 8 + skv) * 32 + lane) * 2) = make_uint2(f2tf(v0), f2tf(v1));
        }
    }
}

// ---------------------------------------------------------------------------
// Kernel 2: flash attention — Q in REGISTERS (R5/R8 finding), non-deferred
// PV with exp/pack INTERLEAVED into the PV mma loop (hides softmax ALU under
// HMMA). K,V double-buffered, prefetch distance = 1 iteration.
// CTA = 128 q-rows, 256 threads. smem 128 KB, 1 CTA/SM, regs ~175.
// Grid 16 x 8; CTA does q-tiles (bx, 31-bx): 66 kv-iters each (balanced).
// ---------------------------------------------------------------------------
#define ATT_SMEM (32768 * 4)   // 131072 B

__global__ __launch_bounds__(256, 1) void attn_mma_kernel(float* __restrict__ out)
{
    extern __shared__ float sm[];
    unsigned* kbu[2] = { (unsigned*)sm,             (unsigned*)(sm + 8192) };
    unsigned* vbu[2] = { (unsigned*)(sm + 16384),   (unsigned*)(sm + 24576) };

    const int t    = threadIdx.x;
    const int w    = t >> 5;       // 0..7
    const int lane = t & 31;
    const int g    = lane >> 2;
    const int tig  = lane & 3;
    const int b    = blockIdx.y;
    const int bx   = blockIdx.x;   // 0..15

#pragma unroll 1
    for (int half = 0; half < 2; half++) {
        const int qt = half ? (31 - bx) : bx;   // 128-row q-tile

        // Q A-frags -> registers (rb = w)
        const unsigned* qg = (const unsigned*)(g_q + (size_t)(b * 32 + qt) * 16384);
        uint4 Q[16];
#pragma unroll
        for (int s = 0; s < 16; s++)
            Q[s] = *(const uint4*)(qg + ((w * 16 + s) * 32 + lane) * 4);

        float4 O[16];
#pragma unroll
        for (int ht = 0; ht < 16; ht++) O[ht] = make_float4(0.f, 0.f, 0.f, 0.f);
        float mrow[2] = {-3.0e38f, -3.0e38f};
        float lrow[2] = {0.f, 0.f};

        const int ntiles = 2 * qt + 2;   // always even

        // prologue: K(0), V(0)
        {
            const float* kg = g_k + (size_t)(b * 64) * 8192;
            const float* vg = g_v + (size_t)(b * 64) * 8192;
#pragma unroll
            for (int u = 0; u < 8; u++) {
                int idx = u * 256 + t;
                cpasync16((float*)kbu[0] + idx * 4, kg + idx * 4);
            }
            CP_COMMIT();
#pragma unroll
            for (int u = 0; u < 8; u++) {
                int idx = u * 256 + t;
                cpasync16((float*)vbu[0] + idx * 4, vg + idx * 4);
            }
            CP_COMMIT();
        }

#pragma unroll 1
        for (int st = 0; st < ntiles; st++) {
            const int p = st & 1;

            cp_wait<0>();          // K(st), V(st) complete
            __syncthreads();

            // prefetch K(st+1), V(st+1) into other buffers
            if (st + 1 < ntiles) {
                const float* kg = g_k + (size_t)(b * 64 + st + 1) * 8192;
                const float* vg = g_v + (size_t)(b * 64 + st + 1) * 8192;
#pragma unroll
                for (int u = 0; u < 8; u++) {
                    int idx = u * 256 + t;
                    cpasync16((float*)kbu[p ^ 1] + idx * 4, kg + idx * 4);
                }
                CP_COMMIT();
#pragma unroll
                for (int u = 0; u < 8; u++) {
                    int idx = u * 256 + t;
                    cpasync16((float*)vbu[p ^ 1] + idx * 4, vg + idx * 4);
                }
                CP_COMMIT();
            }

            // ---- S = Q @ K^T  (16 x 64 per warp; K cols pre-permuted) ----
            const unsigned* ksu = kbu[p];
            float4 sa[8];
#pragma unroll
            for (int j = 0; j < 8; j++) sa[j] = make_float4(0.f, 0.f, 0.f, 0.f);
#pragma unroll
            for (int s = 0; s < 16; s++) {
#pragma unroll
                for (int j = 0; j < 8; j++) {
                    uint2 bf = *(const uint2*)(ksu + ((j * 16 + s) * 32 + lane) * 2);
                    mma_tf32(sa[j], Q[s], bf);
                }
            }

            // ---- causal mask (x<->kv 8j+tig, y<->8j+tig+4) ----
            if (st >= 2 * qt) {
                const int rbase = qt * 128 + w * 16 + g;
#pragma unroll
                for (int j = 0; j < 8; j++) {
                    int kvx = st * 64 + 8 * j + tig;
                    if (kvx     > rbase)     sa[j].x = -1.0e30f;
                    if (kvx + 4 > rbase)     sa[j].y = -1.0e30f;
                    if (kvx     > rbase + 8) sa[j].z = -1.0e30f;
                    if (kvx + 4 > rbase + 8) sa[j].w = -1.0e30f;
                }
            }

            // ---- max + alpha (the only serial pre-PV work) ----
            float alpha[2], mn[2];
#pragma unroll
            for (int h = 0; h < 2; h++) {
                float lm = -3.0e38f;
#pragma unroll
                for (int j = 0; j < 8; j++) {
                    float v0 = h ? sa[j].z : sa[j].x;
                    float v1 = h ? sa[j].w : sa[j].y;
                    lm = fmaxf(lm, fmaxf(v0, v1));
                }
                lm = fmaxf(lm, __shfl_xor_sync(0xffffffffu, lm, 1));
                lm = fmaxf(lm, __shfl_xor_sync(0xffffffffu, lm, 2));
                mn[h]    = fmaxf(mrow[h], lm);
                alpha[h] = __expf(mrow[h] - mn[h]);
                mrow[h]  = mn[h];
            }

            // ---- O rescale ----
#pragma unroll
            for (int ht = 0; ht < 16; ht++) {
                O[ht].x *= alpha[0]; O[ht].y *= alpha[0];
                O[ht].z *= alpha[1]; O[ht].w *= alpha[1];
            }

            // ---- interleaved exp/pack + PV: per j, 4 exp then 16 HMMA ----
            const unsigned* vsu = vbu[p];
            float ls0 = 0.f, ls1 = 0.f;
#pragma unroll
            for (int j = 0; j < 8; j++) {
                float e0 = __expf(sa[j].x - mn[0]);
                float e1 = __expf(sa[j].y - mn[0]);
                float e2 = __expf(sa[j].z - mn[1]);
                float e3 = __expf(sa[j].w - mn[1]);
                ls0 += e0 + e1;
                ls1 += e2 + e3;
                uint4 pa = make_uint4(f2tf(e0), f2tf(e2), f2tf(e1), f2tf(e3));
#pragma unroll
                for (int ht = 0; ht < 16; ht++) {
                    uint2 bf = *(const uint2*)(vsu + ((ht * 8 + j) * 32 + lane) * 2);
                    mma_tf32(O[ht], pa, bf);
                }
            }

            // ---- ls reduction + lrow update (after PV, off critical path) --
            ls0 += __shfl_xor_sync(0xffffffffu, ls0, 1);
            ls0 += __shfl_xor_sync(0xffffffffu, ls0, 2);
            ls1 += __shfl_xor_sync(0xffffffffu, ls1, 1);
            ls1 += __shfl_xor_sync(0xffffffffu, ls1, 2);
            lrow[0] = lrow[0] * alpha[0] + ls0;
            lrow[1] = lrow[1] * alpha[1] + ls1;
        }

        // ---- epilogue: normalize + store ----
        const float inv0 = 1.0f / lrow[0];
        const float inv1 = 1.0f / lrow[1];
        const int r0 = qt * 128 + w * 16 + g;
        float* o0 = out + ((size_t)b * TT + r0) * HH;
        float* o1 = o0 + 8 * HH;
#pragma unroll
        for (int ht = 0; ht < 16; ht++) {
            int col = ht * 8 + 2 * tig;
            *(float2*)(o0 + col) = make_float2(O[ht].x * inv0, O[ht].y * inv0);
            *(float2*)(o1 + col) = make_float2(O[ht].z * inv1, O[ht].w * inv1);
        }
    }
}

// ---------------------------------------------------------------------------
extern "C" void kernel_launch(void* const* d_in, const int* in_sizes, int n_in,
                              void* d_out, int out_size)
{
    const float* x  = (const float*)d_in[0];
    const float* Wq = (const float*)d_in[1];
    const float* bq = (const float*)d_in[2];
    const float* Wk = (const float*)d_in[3];
    const float* bk = (const float*)d_in[4];
    const float* Wv = (const float*)d_in[5];
    const float* bv = (const float*)d_in[6];
    float* out = (float*)d_out;

    cudaFuncSetAttribute(qkv_mma_kernel,
                         cudaFuncAttributeMaxDynamicSharedMemorySize, QKV_SMEM);
    cudaFuncSetAttribute(attn_mma_kernel,
                         cudaFuncAttributeMaxDynamicSharedMemorySize, ATT_SMEM);

    wpack_kernel<<<dim3(32, 3), 256>>>(Wq, Wk, Wv);
    qkv_mma_kernel<<<dim3(MM / 128, 3), 256, QKV_SMEM>>>(x, bq, bk, bv);
    attn_mma_kernel<<<dim3(16, BB), 256, ATT_SMEM>>>(out);
}